// round 3
// baseline (speedup 1.0000x reference)
#include <cuda_runtime.h>
#include <cuda_bf16.h>
#include <math_constants.h>
#include <cstdint>

// ---------------------------------------------------------------------------
// Problem constants
// ---------------------------------------------------------------------------
#define BATCH   8
#define SEQ     1024
#define DIM     768
#define HEADS   12
#define HDIM    64
#define MROWS   (BATCH * SEQ)        // 8192
#define QKVCOLS (3 * DIM)            // 2304

// Scratch (device globals per allocation rules)
__device__ float g_qkv[MROWS * QKVCOLS];   // [8192, 2304] row-major
__device__ float g_attn[MROWS * DIM];      // [8192, 768]  row-major

// ---------------------------------------------------------------------------
// helpers
// ---------------------------------------------------------------------------
__device__ __forceinline__ uint32_t f2tf32(float x) {
    uint32_t r;
    asm("cvt.rna.tf32.f32 %0, %1;" : "=r"(r) : "f"(x));
    return r;
}

__device__ __forceinline__ void mma_tf32(float c[4],
                                         uint32_t a0, uint32_t a1, uint32_t a2, uint32_t a3,
                                         uint32_t b0, uint32_t b1) {
    asm volatile(
        "mma.sync.aligned.m16n8k8.row.col.f32.tf32.tf32.f32 "
        "{%0,%1,%2,%3}, {%4,%5,%6,%7}, {%8,%9}, {%0,%1,%2,%3};\n"
        : "+f"(c[0]), "+f"(c[1]), "+f"(c[2]), "+f"(c[3])
        : "r"(a0), "r"(a1), "r"(a2), "r"(a3), "r"(b0), "r"(b1));
}

__device__ __forceinline__ void cp16(uint32_t dst_smem, const void* src) {
    asm volatile("cp.async.cg.shared.global [%0], [%1], 16;\n"
                 :: "r"(dst_smem), "l"(src) : "memory");
}
__device__ __forceinline__ void cp_commit() {
    asm volatile("cp.async.commit_group;\n" ::: "memory");
}
__device__ __forceinline__ void cp_wait0() {
    asm volatile("cp.async.wait_group 0;\n" ::: "memory");
}

// ---------------------------------------------------------------------------
// TF32 tensor-core GEMM + bias, cp.async pipelined.
// Block 128x128, BK=16, 256 threads = 8 warps (2x4), warp tile 64x32.
// Raw fp32 tiles staged via cp.async (double-buffered); converted smem->smem
// into the single tf32 fragment buffers (As transposed [k][m], Bs [k][n]).
// ---------------------------------------------------------------------------
#define GBM 128
#define GBN 128
#define GBK 16
#define GLDS 136   // padded tf32 row stride; 136 % 32 == 8 -> conflict-free frags

#define GEMM_SMEM_BYTES ((2 * GBM * GBK + 2 * GBK * GBN + 2 * GBK * GLDS) * 4)

__global__ __launch_bounds__(256)
void gemm_tf32_kernel(const float* __restrict__ A,
                      const float* __restrict__ B,
                      const float* __restrict__ bias,
                      float* __restrict__ C,
                      int M, int N, int K) {
    extern __shared__ float gsm[];
    float*    Araw = gsm;                          // [2][128*16]
    float*    Braw = gsm + 2 * GBM * GBK;          // [2][16*128]
    uint32_t* As   = (uint32_t*)(Braw + 2 * GBK * GBN);  // [16][GLDS]
    uint32_t* Bs   = As + GBK * GLDS;                    // [16][GLDS]

    const int tid  = threadIdx.x;
    const int lane = tid & 31;
    const int wid  = tid >> 5;
    const int wr   = wid >> 2;
    const int wc   = wid & 3;
    const int g    = lane >> 2;
    const int t4   = lane & 3;

    const int bRow = blockIdx.y * GBM;
    const int bCol = blockIdx.x * GBN;

    // conversion-pass indices (same as old store pattern)
    const int arow = tid >> 2;           // 0..63
    const int acol = (tid & 3) * 4;      // 0,4,8,12
    const int brow = tid >> 5;           // 0..7
    const int bcol = (tid & 31) * 4;

    const uint32_t araw_s = (uint32_t)__cvta_generic_to_shared(Araw);
    const uint32_t braw_s = (uint32_t)__cvta_generic_to_shared(Braw);

    float acc[4][4][4];
    #pragma unroll
    for (int i = 0; i < 4; ++i)
        #pragma unroll
        for (int j = 0; j < 4; ++j)
            #pragma unroll
            for (int r = 0; r < 4; ++r) acc[i][j][r] = 0.0f;

    const int wmb = wr * 64;
    const int wnb = wc * 32;

    auto issue_tile = [&](int buf, int kb) {
        #pragma unroll
        for (int p = 0; p < 2; ++p) {
            int ch = tid + p * 256;
            int ar = ch >> 2, ak = (ch & 3) << 2;
            cp16(araw_s + (uint32_t)(buf * (GBM * GBK) + ar * GBK + ak) * 4,
                 A + (size_t)(bRow + ar) * K + kb + ak);
            int br = ch >> 5, bn = (ch & 31) << 2;
            cp16(braw_s + (uint32_t)(buf * (GBK * GBN) + br * GBN + bn) * 4,
                 B + (size_t)(kb + br) * N + bCol + bn);
        }
        cp_commit();
    };

    auto convert_tile = [&](int buf) {
        const float* Ab = Araw + buf * (GBM * GBK);
        #pragma unroll
        for (int p = 0; p < 2; ++p) {
            int r = arow + p * 64;
            float4 a4 = *reinterpret_cast<const float4*>(Ab + r * GBK + acol);
            As[(acol + 0) * GLDS + r] = f2tf32(a4.x);
            As[(acol + 1) * GLDS + r] = f2tf32(a4.y);
            As[(acol + 2) * GLDS + r] = f2tf32(a4.z);
            As[(acol + 3) * GLDS + r] = f2tf32(a4.w);
        }
        const float* Bb = Braw + buf * (GBK * GBN);
        #pragma unroll
        for (int p = 0; p < 2; ++p) {
            int r = brow + p * 8;
            float4 b4 = *reinterpret_cast<const float4*>(Bb + r * GBN + bcol);
            uint32_t* dst = &Bs[r * GLDS + bcol];
            dst[0] = f2tf32(b4.x);
            dst[1] = f2tf32(b4.y);
            dst[2] = f2tf32(b4.z);
            dst[3] = f2tf32(b4.w);
        }
    };

    const int nk = K / GBK;
    issue_tile(0, 0);
    cp_wait0();
    __syncthreads();
    convert_tile(0);

    for (int kt = 0; kt < nk; ++kt) {
        __syncthreads();   // tf32 tiles visible to all warps
        if (kt + 1 < nk) issue_tile((kt + 1) & 1, (kt + 1) * GBK);

        #pragma unroll
        for (int ks = 0; ks < 2; ++ks) {
            const int k0 = ks * 8;
            uint32_t af[4][4];
            #pragma unroll
            for (int mt = 0; mt < 4; ++mt) {
                int base = (k0 + t4) * GLDS + wmb + mt * 16 + g;
                af[mt][0] = As[base];
                af[mt][1] = As[base + 8];
                af[mt][2] = As[base + 4 * GLDS];
                af[mt][3] = As[base + 4 * GLDS + 8];
            }
            uint32_t bf[4][2];
            #pragma unroll
            for (int nt = 0; nt < 4; ++nt) {
                int base = (k0 + t4) * GLDS + wnb + nt * 8 + g;
                bf[nt][0] = Bs[base];
                bf[nt][1] = Bs[base + 4 * GLDS];
            }
            #pragma unroll
            for (int mt = 0; mt < 4; ++mt)
                #pragma unroll
                for (int nt = 0; nt < 4; ++nt)
                    mma_tf32(acc[mt][nt], af[mt][0], af[mt][1], af[mt][2], af[mt][3],
                             bf[nt][0], bf[nt][1]);
        }

        if (kt + 1 < nk) {
            cp_wait0();
            __syncthreads();   // all compute done before tf32 buffers overwritten
            convert_tile((kt + 1) & 1);
        }
    }

    // epilogue: bias + store
    #pragma unroll
    for (int nt = 0; nt < 4; ++nt) {
        int c = bCol + wnb + nt * 8 + 2 * t4;
        float bx = bias[c], by = bias[c + 1];
        #pragma unroll
        for (int mt = 0; mt < 4; ++mt) {
            int r0 = bRow + wmb + mt * 16 + g;
            float2 v0 = make_float2(acc[mt][nt][0] + bx, acc[mt][nt][1] + by);
            float2 v1 = make_float2(acc[mt][nt][2] + bx, acc[mt][nt][3] + by);
            *reinterpret_cast<float2*>(C + (size_t)r0 * N + c)       = v0;
            *reinterpret_cast<float2*>(C + (size_t)(r0 + 8) * N + c) = v1;
        }
    }
}

// ---------------------------------------------------------------------------
// Flash attention, tf32 tensor cores, cp.async-prefetched KV.
// One block per (b, h, 64-query tile); 128 threads = 4 warps (16 q each).
// KV tile t+1 staged raw via cp.async during compute of tile t, then
// converted smem->smem into the tf32 fragment buffers.
// ---------------------------------------------------------------------------
#define QK_LD 68
#define V_LD  72
#define ATT_SMEM_BYTES ((3 * 64 * QK_LD + 64 * V_LD + 2 * 64 * 64) * 4)

__global__ __launch_bounds__(128)
void attn_tf32_kernel(const float* __restrict__ qkv, float* __restrict__ out) {
    extern __shared__ uint32_t sm[];
    uint32_t* Qs   = sm;                      // [64][QK_LD]
    uint32_t* Ks   = Qs + 64 * QK_LD;         // [64][QK_LD]
    uint32_t* Ps   = Ks + 64 * QK_LD;         // [64][QK_LD]
    uint32_t* Vs   = Ps + 64 * QK_LD;         // [64][V_LD]
    float*    Kraw = (float*)(Vs + 64 * V_LD);   // [64][64]
    float*    Vraw = Kraw + 64 * 64;             // [64][64]

    const int qt = blockIdx.x;
    const int h  = blockIdx.y;
    const int b  = blockIdx.z;

    const int tid  = threadIdx.x;
    const int lane = tid & 31;
    const int wid  = tid >> 5;
    const int g    = lane >> 2;
    const int t4   = lane & 3;
    const int qw   = wid * 16;

    const float scale = 0.125f;

    const int lrow = tid >> 4;           // 0..7
    const int lcol = (tid & 15) * 4;

    const uint32_t kraw_s = (uint32_t)__cvta_generic_to_shared(Kraw);
    const uint32_t vraw_s = (uint32_t)__cvta_generic_to_shared(Vraw);

    auto issue_kv = [&](int t) {
        const float* kb_ = qkv + ((size_t)(b * SEQ + t * 64)) * QKVCOLS + DIM + h * HDIM;
        const float* vb_ = kb_ + DIM;
        #pragma unroll
        for (int rr = lrow; rr < 64; rr += 8) {
            cp16(kraw_s + (uint32_t)(rr * 64 + lcol) * 4, kb_ + (size_t)rr * QKVCOLS + lcol);
            cp16(vraw_s + (uint32_t)(rr * 64 + lcol) * 4, vb_ + (size_t)rr * QKVCOLS + lcol);
        }
        cp_commit();
    };

    auto convert_kv = [&]() {
        #pragma unroll
        for (int rr = lrow; rr < 64; rr += 8) {
            float4 k4 = *reinterpret_cast<const float4*>(Kraw + rr * 64 + lcol);
            Ks[rr * QK_LD + lcol + 0] = f2tf32(k4.x);
            Ks[rr * QK_LD + lcol + 1] = f2tf32(k4.y);
            Ks[rr * QK_LD + lcol + 2] = f2tf32(k4.z);
            Ks[rr * QK_LD + lcol + 3] = f2tf32(k4.w);
            float4 v4 = *reinterpret_cast<const float4*>(Vraw + rr * 64 + lcol);
            Vs[rr * V_LD + lcol + 0] = f2tf32(v4.x);
            Vs[rr * V_LD + lcol + 1] = f2tf32(v4.y);
            Vs[rr * V_LD + lcol + 2] = f2tf32(v4.z);
            Vs[rr * V_LD + lcol + 3] = f2tf32(v4.w);
        }
    };

    // Q tile (once): LDG -> cvt -> STS, pre-scaled
    {
        const float* qbase = qkv + ((size_t)(b * SEQ + qt * 64)) * QKVCOLS + h * HDIM;
        #pragma unroll
        for (int rr = lrow; rr < 64; rr += 8) {
            float4 q4 = *reinterpret_cast<const float4*>(qbase + (size_t)rr * QKVCOLS + lcol);
            Qs[rr * QK_LD + lcol + 0] = f2tf32(q4.x * scale);
            Qs[rr * QK_LD + lcol + 1] = f2tf32(q4.y * scale);
            Qs[rr * QK_LD + lcol + 2] = f2tf32(q4.z * scale);
            Qs[rr * QK_LD + lcol + 3] = f2tf32(q4.w * scale);
        }
    }

    float m_i[2] = {-CUDART_INF_F, -CUDART_INF_F};
    float l_i[2] = {0.0f, 0.0f};
    float oacc[8][4];
    #pragma unroll
    for (int nt = 0; nt < 8; ++nt)
        #pragma unroll
        for (int r = 0; r < 4; ++r) oacc[nt][r] = 0.0f;

    const int NT = SEQ / 64;
    issue_kv(0);
    cp_wait0();
    __syncthreads();
    convert_kv();

    for (int t = 0; t < NT; ++t) {
        __syncthreads();   // Ks/Vs (and Qs on t==0) visible to all warps
        if (t + 1 < NT) issue_kv(t + 1);

        // --- S = Q @ K^T ---
        float sacc[8][4];
        #pragma unroll
        for (int nt = 0; nt < 8; ++nt)
            #pragma unroll
            for (int r = 0; r < 4; ++r) sacc[nt][r] = 0.0f;

        #pragma unroll
        for (int ks = 0; ks < 8; ++ks) {
            int ab = (qw + g) * QK_LD + ks * 8 + t4;
            uint32_t a0 = Qs[ab];
            uint32_t a1 = Qs[ab + 8 * QK_LD];
            uint32_t a2 = Qs[ab + 4];
            uint32_t a3 = Qs[ab + 8 * QK_LD + 4];
            #pragma unroll
            for (int nt = 0; nt < 8; ++nt) {
                int bb = (nt * 8 + g) * QK_LD + ks * 8 + t4;
                mma_tf32(sacc[nt], a0, a1, a2, a3, Ks[bb], Ks[bb + 4]);
            }
        }

        // --- online softmax (row-halves g and g+8) ---
        #pragma unroll
        for (int rh = 0; rh < 2; ++rh) {
            float mx = -CUDART_INF_F;
            #pragma unroll
            for (int nt = 0; nt < 8; ++nt)
                mx = fmaxf(mx, fmaxf(sacc[nt][rh * 2], sacc[nt][rh * 2 + 1]));
            mx = fmaxf(mx, __shfl_xor_sync(0xffffffffu, mx, 1));
            mx = fmaxf(mx, __shfl_xor_sync(0xffffffffu, mx, 2));
            float mnew  = fmaxf(m_i[rh], mx);
            float alpha = __expf(m_i[rh] - mnew);
            float rsum = 0.0f;
            int prow = (qw + g + rh * 8) * QK_LD;
            #pragma unroll
            for (int nt = 0; nt < 8; ++nt) {
                float p0 = __expf(sacc[nt][rh * 2]     - mnew);
                float p1 = __expf(sacc[nt][rh * 2 + 1] - mnew);
                rsum += p0 + p1;
                Ps[prow + nt * 8 + 2 * t4]     = f2tf32(p0);
                Ps[prow + nt * 8 + 2 * t4 + 1] = f2tf32(p1);
            }
            rsum += __shfl_xor_sync(0xffffffffu, rsum, 1);
            rsum += __shfl_xor_sync(0xffffffffu, rsum, 2);
            l_i[rh] = l_i[rh] * alpha + rsum;
            m_i[rh] = mnew;
            #pragma unroll
            for (int nt = 0; nt < 8; ++nt) {
                oacc[nt][rh * 2]     *= alpha;
                oacc[nt][rh * 2 + 1] *= alpha;
            }
        }
        __syncwarp();

        // --- O += P @ V ---
        #pragma unroll
        for (int ks = 0; ks < 8; ++ks) {
            int ab = (qw + g) * QK_LD + ks * 8 + t4;
            uint32_t a0 = Ps[ab];
            uint32_t a1 = Ps[ab + 8 * QK_LD];
            uint32_t a2 = Ps[ab + 4];
            uint32_t a3 = Ps[ab + 8 * QK_LD + 4];
            #pragma unroll
            for (int nt = 0; nt < 8; ++nt) {
                int bb = (ks * 8 + t4) * V_LD + nt * 8 + g;
                mma_tf32(oacc[nt], a0, a1, a2, a3, Vs[bb], Vs[bb + 4 * V_LD]);
            }
        }

        if (t + 1 < NT) {
            cp_wait0();
            __syncthreads();   // compute done before Ks/Vs overwritten
            convert_kv();
        }
    }

    // normalize + write [B, N, C]
    #pragma unroll
    for (int rh = 0; rh < 2; ++rh) {
        float inv = 1.0f / l_i[rh];
        size_t row = (size_t)(b * SEQ + qt * 64 + qw + g + rh * 8);
        #pragma unroll
        for (int nt = 0; nt < 8; ++nt) {
            float2 v = make_float2(oacc[nt][rh * 2] * inv, oacc[nt][rh * 2 + 1] * inv);
            *reinterpret_cast<float2*>(out + row * DIM + h * HDIM + nt * 8 + 2 * t4) = v;
        }
    }
}

// ---------------------------------------------------------------------------
// Launch
// ---------------------------------------------------------------------------
extern "C" void kernel_launch(void* const* d_in, const int* in_sizes, int n_in,
                              void* d_out, int out_size) {
    const float* x      = (const float*)d_in[0];
    const float* w_qkv  = (const float*)d_in[1];
    const float* b_qkv  = (const float*)d_in[2];
    const float* w_proj = (const float*)d_in[3];
    const float* b_proj = (const float*)d_in[4];
    float* out = (float*)d_out;

    float* qkv;
    float* attn;
    cudaGetSymbolAddress((void**)&qkv,  g_qkv);
    cudaGetSymbolAddress((void**)&attn, g_attn);

    cudaFuncSetAttribute(gemm_tf32_kernel,
                         cudaFuncAttributeMaxDynamicSharedMemorySize,
                         GEMM_SMEM_BYTES);
    cudaFuncSetAttribute(attn_tf32_kernel,
                         cudaFuncAttributeMaxDynamicSharedMemorySize,
                         ATT_SMEM_BYTES);

    // 1) QKV projection
    {
        dim3 grid(QKVCOLS / GBN, MROWS / GBM);
        gemm_tf32_kernel<<<grid, 256, GEMM_SMEM_BYTES>>>(x, w_qkv, b_qkv, qkv,
                                                         MROWS, QKVCOLS, DIM);
    }
    // 2) Flash attention
    {
        dim3 grid(SEQ / 64, HEADS, BATCH);
        attn_tf32_kernel<<<grid, 128, ATT_SMEM_BYTES>>>(qkv, attn);
    }
    // 3) Output projection
    {
        dim3 grid(DIM / GBN, MROWS / GBM);
        gemm_tf32_kernel<<<grid, 256, GEMM_SMEM_BYTES>>>(attn, w_proj, b_proj, out,
                                                         MROWS, DIM, DIM);
    }
}

// round 5
// speedup vs baseline: 1.3633x; 1.3633x over previous
#include <cuda_runtime.h>
#include <cuda_bf16.h>
#include <math_constants.h>
#include <cstdint>

// ---------------------------------------------------------------------------
// Problem constants
// ---------------------------------------------------------------------------
#define BATCH   8
#define SEQ     1024
#define DIM     768
#define HEADS   12
#define HDIM    64
#define MROWS   (BATCH * SEQ)        // 8192
#define QKVCOLS (3 * DIM)            // 2304

// Scratch (device globals per allocation rules)
__device__ float g_qkv[MROWS * QKVCOLS];     // [8192, 2304] tf32 bits
__device__ float g_attn[MROWS * DIM];        // [8192, 768]  tf32 bits
__device__ float g_xt[MROWS * DIM];          // x as tf32 bits
__device__ float g_w1[DIM * QKVCOLS];        // w_qkv tf32 bits
__device__ float g_w2[DIM * DIM];            // w_proj tf32 bits

// ---------------------------------------------------------------------------
// helpers
// ---------------------------------------------------------------------------
__device__ __forceinline__ uint32_t f2tf32(float x) {
    uint32_t r;
    asm("cvt.rna.tf32.f32 %0, %1;" : "=r"(r) : "f"(x));
    return r;
}
__device__ __forceinline__ float fexp2(float x) {
    float y;
    asm("ex2.approx.f32 %0, %1;" : "=f"(y) : "f"(x));
    return y;
}
__device__ __forceinline__ void mma_tf32(float c[4],
                                         uint32_t a0, uint32_t a1, uint32_t a2, uint32_t a3,
                                         uint32_t b0, uint32_t b1) {
    asm volatile(
        "mma.sync.aligned.m16n8k8.row.col.f32.tf32.tf32.f32 "
        "{%0,%1,%2,%3}, {%4,%5,%6,%7}, {%8,%9}, {%0,%1,%2,%3};\n"
        : "+f"(c[0]), "+f"(c[1]), "+f"(c[2]), "+f"(c[3])
        : "r"(a0), "r"(a1), "r"(a2), "r"(a3), "r"(b0), "r"(b1));
}
__device__ __forceinline__ void cp16(uint32_t dst_smem, const void* src) {
    asm volatile("cp.async.cg.shared.global [%0], [%1], 16;\n"
                 :: "r"(dst_smem), "l"(src) : "memory");
}
__device__ __forceinline__ void cp_commit() {
    asm volatile("cp.async.commit_group;\n" ::: "memory");
}
__device__ __forceinline__ void cp_wait0() {
    asm volatile("cp.async.wait_group 0;\n" ::: "memory");
}

// ---------------------------------------------------------------------------
// tf32 pre-conversion (element-wise, float4)
// ---------------------------------------------------------------------------
__global__ __launch_bounds__(256)
void cvt_tf32_kernel(const float* __restrict__ in, float* __restrict__ out, int n4) {
    int i = blockIdx.x * 256 + threadIdx.x;
    if (i < n4) {
        float4 v = reinterpret_cast<const float4*>(in)[i];
        uint4 o;
        o.x = f2tf32(v.x); o.y = f2tf32(v.y); o.z = f2tf32(v.z); o.w = f2tf32(v.w);
        reinterpret_cast<uint4*>(out)[i] = o;
    }
}

// ---------------------------------------------------------------------------
// TF32 mma.sync GEMM + bias: C[M,N] = A[M,K]*B[K,N] + bias[N]
// A, B are PRE-CONVERTED tf32 bits. Block 128x128, 4 warps (2x2), warp 64x64,
// BK=32, cp.async double-buffered directly into MMA layouts:
//   A: [m][k] stride 36 (conflict-free stores + frag loads)
//   B: [k][n] stride 136
// store_tf32 != 0 -> output written as tf32 bits (for downstream MMA consumers)
// ---------------------------------------------------------------------------
#define GA_LDK 36
#define GB_LDN 136
#define G_AW   (128 * GA_LDK)       // 4608 words per A buffer
#define G_BW   (32 * GB_LDN)        // 4352 words per B buffer
#define GEMM_SMEM_BYTES ((2 * G_AW + 2 * G_BW) * 4)   // 71680

__global__ __launch_bounds__(128)
void gemm_tf32_kernel(const float* __restrict__ A,
                      const float* __restrict__ B,
                      const float* __restrict__ bias,
                      float* __restrict__ C,
                      int M, int N, int K, int store_tf32) {
    extern __shared__ uint32_t gsm[];
    const uint32_t sbytes = (uint32_t)__cvta_generic_to_shared(gsm);

    const int tid  = threadIdx.x;
    const int lane = tid & 31;
    const int wid  = tid >> 5;          // 0..3
    const int wr   = wid >> 1;          // 0..1 -> row base 64*wr
    const int wc   = wid & 1;           // 0..1 -> col base 64*wc
    const int g    = lane >> 2;         // 0..7
    const int t4   = lane & 3;          // 0..3

    const int bRow = blockIdx.y * 128;
    const int bCol = blockIdx.x * 128;

    auto issue_tile = [&](int buf, int kb) {
        const uint32_t abase = sbytes + (uint32_t)buf * G_AW * 4;
        const uint32_t bbase = sbytes + (uint32_t)(2 * G_AW + buf * G_BW) * 4;
        #pragma unroll
        for (int i = 0; i < 8; ++i) {
            int ch = tid + i * 128;
            int am = ch >> 3, ak = (ch & 7) * 4;        // A: 128 rows x 8 chunks
            cp16(abase + (uint32_t)(am * GA_LDK + ak) * 4,
                 A + (size_t)(bRow + am) * K + kb + ak);
            int bk = ch >> 5, bn = (ch & 31) * 4;        // B: 32 rows x 32 chunks
            cp16(bbase + (uint32_t)(bk * GB_LDN + bn) * 4,
                 B + (size_t)(kb + bk) * N + bCol + bn);
        }
        cp_commit();
    };

    float acc[4][8][4];
    #pragma unroll
    for (int mt = 0; mt < 4; ++mt)
        #pragma unroll
        for (int nt = 0; nt < 8; ++nt)
            #pragma unroll
            for (int r = 0; r < 4; ++r) acc[mt][nt][r] = 0.0f;

    const int NK = K / 32;
    issue_tile(0, 0);

    for (int t = 0; t < NK; ++t) {
        cp_wait0();
        __syncthreads();                         // buffer t ready; compute t-1 done
        if (t + 1 < NK) issue_tile((t + 1) & 1, (t + 1) * 32);

        const uint32_t* Ab = gsm + (t & 1) * G_AW;
        const uint32_t* Bb = gsm + 2 * G_AW + (t & 1) * G_BW;

        #pragma unroll
        for (int ks = 0; ks < 4; ++ks) {
            const int k0 = ks * 8;
            uint32_t af[4][4];
            #pragma unroll
            for (int mt = 0; mt < 4; ++mt) {
                int base = (wr * 64 + mt * 16 + g) * GA_LDK + k0 + t4;
                af[mt][0] = Ab[base];
                af[mt][1] = Ab[base + 8 * GA_LDK];
                af[mt][2] = Ab[base + 4];
                af[mt][3] = Ab[base + 8 * GA_LDK + 4];
            }
            #pragma unroll
            for (int nt = 0; nt < 8; ++nt) {
                int bb = (k0 + t4) * GB_LDN + wc * 64 + nt * 8 + g;
                uint32_t b0 = Bb[bb];
                uint32_t b1 = Bb[bb + 4 * GB_LDN];
                #pragma unroll
                for (int mt = 0; mt < 4; ++mt)
                    mma_tf32(acc[mt][nt], af[mt][0], af[mt][1], af[mt][2], af[mt][3],
                             b0, b1);
            }
        }
    }

    // epilogue: bias + store
    #pragma unroll
    for (int nt = 0; nt < 8; ++nt) {
        int c = bCol + wc * 64 + nt * 8 + 2 * t4;
        float bx = bias[c], by = bias[c + 1];
        #pragma unroll
        for (int mt = 0; mt < 4; ++mt) {
            int r0 = bRow + wr * 64 + mt * 16 + g;
            float2 v0 = make_float2(acc[mt][nt][0] + bx, acc[mt][nt][1] + by);
            float2 v1 = make_float2(acc[mt][nt][2] + bx, acc[mt][nt][3] + by);
            if (store_tf32) {
                v0.x = __uint_as_float(f2tf32(v0.x));
                v0.y = __uint_as_float(f2tf32(v0.y));
                v1.x = __uint_as_float(f2tf32(v1.x));
                v1.y = __uint_as_float(f2tf32(v1.y));
            }
            *reinterpret_cast<float2*>(C + (size_t)r0 * N + c)       = v0;
            *reinterpret_cast<float2*>(C + (size_t)(r0 + 8) * N + c) = v1;
        }
    }
}

// ---------------------------------------------------------------------------
// Flash attention, tf32 mma.sync. Block = 128 queries (4 warps x 32q),
// 64-key tiles streamed via cp.async (KV already tf32 bits in g_qkv).
// Softmax in exp2 domain (log2e folded into Q scale). Output tf32 bits.
// ---------------------------------------------------------------------------
#define AQ_LD 68
#define AV_LD 72
#define ATT_SMEM_BYTES ((128 * AQ_LD + 64 * AQ_LD + 128 * AQ_LD + 64 * AV_LD) * 4)

__global__ __launch_bounds__(128)
void attn_tf32_kernel(const float* __restrict__ qkv, float* __restrict__ out) {
    extern __shared__ uint32_t sm[];
    uint32_t* Qs = sm;                        // [128][AQ_LD]
    uint32_t* Ks = Qs + 128 * AQ_LD;          // [64][AQ_LD]
    uint32_t* Ps = Ks + 64 * AQ_LD;           // [128][AQ_LD]
    uint32_t* Vs = Ps + 128 * AQ_LD;          // [64][AV_LD]

    const int qt = blockIdx.x;                // 128-query tile, 0..7
    const int h  = blockIdx.y;
    const int b  = blockIdx.z;

    const int tid  = threadIdx.x;
    const int lane = tid & 31;
    const int wid  = tid >> 5;                // 0..3
    const int g    = lane >> 2;
    const int t4   = lane & 3;
    const int qw   = wid * 32;                // warp's 32-query base

    const float SC = 0.125f * 1.44269504088896341f;   // scale * log2(e)

    const int lrow = tid >> 4;                // 0..7
    const int lcol = (tid & 15) * 4;

    const uint32_t ks_b = (uint32_t)__cvta_generic_to_shared(Ks);
    const uint32_t vs_b = (uint32_t)__cvta_generic_to_shared(Vs);

    // Q: 128 rows, loaded once (scaled, re-rounded to tf32)
    {
        const float* qbase = qkv + ((size_t)(b * SEQ + qt * 128)) * QKVCOLS + h * HDIM;
        #pragma unroll
        for (int rr = lrow; rr < 128; rr += 8) {
            float4 q4 = *reinterpret_cast<const float4*>(qbase + (size_t)rr * QKVCOLS + lcol);
            Qs[rr * AQ_LD + lcol + 0] = f2tf32(q4.x * SC);
            Qs[rr * AQ_LD + lcol + 1] = f2tf32(q4.y * SC);
            Qs[rr * AQ_LD + lcol + 2] = f2tf32(q4.z * SC);
            Qs[rr * AQ_LD + lcol + 3] = f2tf32(q4.w * SC);
        }
    }

    float m_i[2][2], l_i[2][2];
    float oacc[2][8][4];
    #pragma unroll
    for (int mt = 0; mt < 2; ++mt) {
        m_i[mt][0] = m_i[mt][1] = -CUDART_INF_F;
        l_i[mt][0] = l_i[mt][1] = 0.0f;
        #pragma unroll
        for (int nt = 0; nt < 8; ++nt)
            #pragma unroll
            for (int r = 0; r < 4; ++r) oacc[mt][nt][r] = 0.0f;
    }

    for (int t = 0; t < SEQ / 64; ++t) {
        __syncthreads();   // prior tile's PV reads done (covers Qs on t==0)

        // cp.async K and V tiles (already tf32 bits — straight copy)
        {
            const float* kb_ = qkv + ((size_t)(b * SEQ + t * 64)) * QKVCOLS + DIM + h * HDIM;
            const float* vb_ = kb_ + DIM;
            #pragma unroll
            for (int rr = lrow; rr < 64; rr += 8) {
                cp16(ks_b + (uint32_t)(rr * AQ_LD + lcol) * 4, kb_ + (size_t)rr * QKVCOLS + lcol);
                cp16(vs_b + (uint32_t)(rr * AV_LD + lcol) * 4, vb_ + (size_t)rr * QKVCOLS + lcol);
            }
            cp_commit();
            cp_wait0();
        }
        __syncthreads();

        // --- S = Q @ K^T  (32q x 64k per warp) ---
        float sacc[2][8][4];
        #pragma unroll
        for (int mt = 0; mt < 2; ++mt)
            #pragma unroll
            for (int nt = 0; nt < 8; ++nt)
                #pragma unroll
                for (int r = 0; r < 4; ++r) sacc[mt][nt][r] = 0.0f;

        #pragma unroll
        for (int ks = 0; ks < 8; ++ks) {
            uint32_t af[2][4];
            #pragma unroll
            for (int mt = 0; mt < 2; ++mt) {
                int ab = (qw + mt * 16 + g) * AQ_LD + ks * 8 + t4;
                af[mt][0] = Qs[ab];
                af[mt][1] = Qs[ab + 8 * AQ_LD];
                af[mt][2] = Qs[ab + 4];
                af[mt][3] = Qs[ab + 8 * AQ_LD + 4];
            }
            #pragma unroll
            for (int nt = 0; nt < 8; ++nt) {
                int bb = (nt * 8 + g) * AQ_LD + ks * 8 + t4;
                uint32_t b0 = Ks[bb];
                uint32_t b1 = Ks[bb + 4];
                #pragma unroll
                for (int mt = 0; mt < 2; ++mt)
                    mma_tf32(sacc[mt][nt], af[mt][0], af[mt][1], af[mt][2], af[mt][3],
                             b0, b1);
            }
        }

        // --- online softmax (exp2 domain), P -> smem ---
        #pragma unroll
        for (int mt = 0; mt < 2; ++mt) {
            #pragma unroll
            for (int rh = 0; rh < 2; ++rh) {
                float mx = -CUDART_INF_F;
                #pragma unroll
                for (int nt = 0; nt < 8; ++nt)
                    mx = fmaxf(mx, fmaxf(sacc[mt][nt][rh * 2], sacc[mt][nt][rh * 2 + 1]));
                mx = fmaxf(mx, __shfl_xor_sync(0xffffffffu, mx, 1));
                mx = fmaxf(mx, __shfl_xor_sync(0xffffffffu, mx, 2));
                float mnew  = fmaxf(m_i[mt][rh], mx);
                float alpha = fexp2(m_i[mt][rh] - mnew);
                float rsum = 0.0f;
                int prow = (qw + mt * 16 + rh * 8 + g) * AQ_LD;
                #pragma unroll
                for (int nt = 0; nt < 8; ++nt) {
                    float p0 = fexp2(sacc[mt][nt][rh * 2]     - mnew);
                    float p1 = fexp2(sacc[mt][nt][rh * 2 + 1] - mnew);
                    rsum += p0 + p1;
                    Ps[prow + nt * 8 + 2 * t4]     = f2tf32(p0);
                    Ps[prow + nt * 8 + 2 * t4 + 1] = f2tf32(p1);
                }
                rsum += __shfl_xor_sync(0xffffffffu, rsum, 1);
                rsum += __shfl_xor_sync(0xffffffffu, rsum, 2);
                l_i[mt][rh] = l_i[mt][rh] * alpha + rsum;
                m_i[mt][rh] = mnew;
                #pragma unroll
                for (int nt = 0; nt < 8; ++nt) {
                    oacc[mt][nt][rh * 2]     *= alpha;
                    oacc[mt][nt][rh * 2 + 1] *= alpha;
                }
            }
        }
        __syncwarp();   // P rows are warp-private

        // --- O += P @ V ---
        #pragma unroll
        for (int ks = 0; ks < 8; ++ks) {
            uint32_t af[2][4];
            #pragma unroll
            for (int mt = 0; mt < 2; ++mt) {
                int ab = (qw + mt * 16 + g) * AQ_LD + ks * 8 + t4;
                af[mt][0] = Ps[ab];
                af[mt][1] = Ps[ab + 8 * AQ_LD];
                af[mt][2] = Ps[ab + 4];
                af[mt][3] = Ps[ab + 8 * AQ_LD + 4];
            }
            #pragma unroll
            for (int nt = 0; nt < 8; ++nt) {
                int bb = (ks * 8 + t4) * AV_LD + nt * 8 + g;
                uint32_t b0 = Vs[bb];
                uint32_t b1 = Vs[bb + 4 * AV_LD];
                #pragma unroll
                for (int mt = 0; mt < 2; ++mt)
                    mma_tf32(oacc[mt][nt], af[mt][0], af[mt][1], af[mt][2], af[mt][3],
                             b0, b1);
            }
        }
    }

    // normalize + write tf32 bits to g_attn [B, N, C]
    #pragma unroll
    for (int mt = 0; mt < 2; ++mt) {
        #pragma unroll
        for (int rh = 0; rh < 2; ++rh) {
            float inv = 1.0f / l_i[mt][rh];
            size_t row = (size_t)(b * SEQ + qt * 128 + qw + mt * 16 + rh * 8 + g);
            #pragma unroll
            for (int nt = 0; nt < 8; ++nt) {
                float2 v;
                v.x = __uint_as_float(f2tf32(oacc[mt][nt][rh * 2]     * inv));
                v.y = __uint_as_float(f2tf32(oacc[mt][nt][rh * 2 + 1] * inv));
                *reinterpret_cast<float2*>(out + row * DIM + h * HDIM + nt * 8 + 2 * t4) = v;
            }
        }
    }
}

// ---------------------------------------------------------------------------
// Launch
// ---------------------------------------------------------------------------
extern "C" void kernel_launch(void* const* d_in, const int* in_sizes, int n_in,
                              void* d_out, int out_size) {
    const float* x      = (const float*)d_in[0];
    const float* w_qkv  = (const float*)d_in[1];
    const float* b_qkv  = (const float*)d_in[2];
    const float* w_proj = (const float*)d_in[3];
    const float* b_proj = (const float*)d_in[4];
    float* out = (float*)d_out;

    float *qkv, *attn, *xt, *w1, *w2;
    cudaGetSymbolAddress((void**)&qkv,  g_qkv);
    cudaGetSymbolAddress((void**)&attn, g_attn);
    cudaGetSymbolAddress((void**)&xt,   g_xt);
    cudaGetSymbolAddress((void**)&w1,   g_w1);
    cudaGetSymbolAddress((void**)&w2,   g_w2);

    cudaFuncSetAttribute(gemm_tf32_kernel,
                         cudaFuncAttributeMaxDynamicSharedMemorySize, GEMM_SMEM_BYTES);
    cudaFuncSetAttribute(attn_tf32_kernel,
                         cudaFuncAttributeMaxDynamicSharedMemorySize, ATT_SMEM_BYTES);

    // 0) pre-convert inputs/weights to tf32 bits
    {
        int n4x = (MROWS * DIM) / 4;
        cvt_tf32_kernel<<<(n4x + 255) / 256, 256>>>(x, xt, n4x);
        int n4w1 = (DIM * QKVCOLS) / 4;
        cvt_tf32_kernel<<<(n4w1 + 255) / 256, 256>>>(w_qkv, w1, n4w1);
        int n4w2 = (DIM * DIM) / 4;
        cvt_tf32_kernel<<<(n4w2 + 255) / 256, 256>>>(w_proj, w2, n4w2);
    }

    // 1) QKV projection (tf32-bit output for attention MMA consumers)
    gemm_tf32_kernel<<<dim3(QKVCOLS / 128, MROWS / 128), 128, GEMM_SMEM_BYTES>>>(
        xt, w1, b_qkv, qkv, MROWS, QKVCOLS, DIM, 1);

    // 2) Flash attention (tf32-bit output for proj GEMM)
    attn_tf32_kernel<<<dim3(SEQ / 128, HEADS, BATCH), 128, ATT_SMEM_BYTES>>>(qkv, attn);

    // 3) Output projection (plain fp32 output)
    gemm_tf32_kernel<<<dim3(DIM / 128, MROWS / 128), 128, GEMM_SMEM_BYTES>>>(
        attn, w2, b_proj, out, MROWS, DIM, DIM, 0);
}